// round 16
// baseline (speedup 1.0000x reference)
#include <cuda_runtime.h>
#include <cuda_bf16.h>
#include <cstdint>

// BigramLM fused kernel for GB300 (sm_103a) — fp16 HMMA + fused mini-prologue.
//  - Linearity: x = tok_emb[tok]+pos_emb[s] => proj tables split into
//    (tok_emb@W)[tok] + (pos_emb@W)[s]. Whole prologue = ONE small kernel.
//  - QK table stores exp(q.k*scale); attention fp32, adds+fma only.
//  - 512 threads persistent (4 warps/SMSP), warp-decoupled 32-row tiles.
//  - GEMMs single-term fp16 (rel_err ~4e-4 < 1e-3 gate), 52 HMMA/tile.
//  - B fragments packed as one uint4 per (nt,lane) covering both k-blocks.
//  - QK-table lookups prefetched one tile ahead (drain behind GEMM phase).
//  - VT built in-kernel from raw inputs (no g_v global round-trip).

#define VOCAB 65
#define NE    32
#define TT    8
#define NROWTAB 520
#define VT_STRIDE 36
#define NWARP 16

// ---- smem byte offsets (main kernel) ----
#define OFF_BF     0          // 32 f
#define OFF_BL     128        // 72 f
#define OFF_B1P    416        // 128 uint4 = 2048
#define OFF_B2P    2464       // 288 uint4 = 4608
#define OFF_VT     7072       // 520*36 f = 74880
#define OFF_WARP   81952      // 16 warps * 4224 (XW 32*20 words / ST 16*65 f, aliased)
#define WARP_BYTES 4224
#define SMEM_TOTAL (81952 + NWARP * WARP_BYTES)   // 149536

// ---------------- scratch ----------------
__device__ float4 g_qk[TT * VOCAB * TT * VOCAB];   // exp(dot*scale), 4 heads

// ---------------- helpers ----------------
__device__ __forceinline__ uint32_t pkhf(float lo, float hi) {
    uint32_t r;
    asm("{ .reg .f16 l, h;\n\t"
        "cvt.rn.f16.f32 l, %1;\n\t"
        "cvt.rn.f16.f32 h, %2;\n\t"
        "mov.b32 %0, {l, h}; }"
        : "=r"(r) : "f"(lo), "f"(hi));
    return r;
}
__device__ __forceinline__ void mma16816(float* d, const uint32_t* a,
                                         uint32_t b0, uint32_t b1) {
    asm volatile(
        "mma.sync.aligned.m16n8k16.row.col.f32.f16.f16.f32 "
        "{%0,%1,%2,%3}, {%4,%5,%6,%7}, {%8,%9}, {%0,%1,%2,%3};"
        : "+f"(d[0]), "+f"(d[1]), "+f"(d[2]), "+f"(d[3])
        : "r"(a[0]), "r"(a[1]), "r"(a[2]), "r"(a[3]), "r"(b0), "r"(b1));
}

// ---------------- fused prologue: QK exp table (64 blocks = (t,s)) ----------------
__global__ void build_qk_fused(const float* __restrict__ tok_emb,
                               const float* __restrict__ pos_emb,
                               const float* __restrict__ Wq,
                               const float* __restrict__ Wk) {
    __shared__ float TE[VOCAB * NE];        // 2080
    __shared__ float WQ[1024], WK[1024];
    __shared__ float PEt[NE], PEs[NE];
    __shared__ float SQ[VOCAB * 33];        // q rows at position t (pad 33)
    __shared__ float SK[VOCAB * 33];        // k rows at position s

    const int tid = threadIdx.x;
    const int t = blockIdx.x >> 3, s = blockIdx.x & 7;

    for (int i = tid; i < VOCAB * NE; i += 256) TE[i] = tok_emb[i];
    for (int i = tid; i < 1024; i += 256) { WQ[i] = Wq[i]; WK[i] = Wk[i]; }
    if (tid < NE) {
        PEt[tid] = pos_emb[t * NE + tid];
        PEs[tid] = pos_emb[s * NE + tid];
    }
    __syncthreads();

    // q[tok][n] = sum_c (TE[tok][c]+PEt[c]) * Wq[h][c][d],  n = h*8+d
    for (int i = tid; i < VOCAB * NE; i += 256) {
        int tok = i >> 5, n = i & 31;
        int h = n >> 3, d = n & 7;
        float qa = 0.f, ka = 0.f;
        #pragma unroll
        for (int c = 0; c < NE; c++) {
            float te = TE[tok * NE + c];
            int wi = (h * NE + c) * 8 + d;
            qa = fmaf(te + PEt[c], WQ[wi], qa);
            ka = fmaf(te + PEs[c], WK[wi], ka);
        }
        SQ[tok * 33 + n] = qa;
        SK[tok * 33 + n] = ka;
    }
    __syncthreads();

    // exp-dots for all (tokt, toks)
    for (int i = tid; i < VOCAB * VOCAB; i += 256) {
        int tokt = i / VOCAB, toks = i - tokt * VOCAB;
        float4 o;
        float* op = &o.x;
        #pragma unroll
        for (int h = 0; h < 4; h++) {
            float acc = 0.f;
            #pragma unroll
            for (int d = 0; d < 8; d++)
                acc = fmaf(SQ[tokt * 33 + h * 8 + d], SK[toks * 33 + h * 8 + d], acc);
            op[h] = __expf(acc * 0.17677669529663687f);
        }
        g_qk[((t * VOCAB + tokt) * 8 + s) * VOCAB + toks] = o;
    }
}

// ---------------- main persistent kernel ----------------
__global__ void __launch_bounds__(512, 1)
bigram_main(const int*   __restrict__ idx,
            const float* __restrict__ tok_emb,
            const float* __restrict__ pos_emb,
            const float* __restrict__ Wv,
            const float* __restrict__ Wf,
            const float* __restrict__ bf,
            const float* __restrict__ Wl,
            const float* __restrict__ bl,
            float*       __restrict__ out,
            int n_wtiles) {
    extern __shared__ char sm[];
    float* BFs = (float*)(sm + OFF_BF);
    float* BLs = (float*)(sm + OFF_BL);
    uint4* B1P = (uint4*)(sm + OFF_B1P);
    uint4* B2P = (uint4*)(sm + OFF_B2P);
    float* VT  = (float*)(sm + OFF_VT);
    float* SCR = (float*)(sm + OFF_WARP);   // init-time scratch (warp regions, dead pre-loop)
    const int tid = threadIdx.x;

    // ---- one-time init: VT from raw inputs via linearity ----
    float* sTE = SCR;            // 2080
    float* sWV = SCR + 2080;     // 1024
    float* sTV = SCR + 3104;     // 2080: (tok_emb@Wv)
    float* sPV = SCR + 5184;     // 256 : (pos_emb@Wv)
    for (int i = tid; i < VOCAB * NE; i += 512) sTE[i] = tok_emb[i];
    for (int i = tid; i < 1024; i += 512) sWV[i] = Wv[i];
    if (tid < 32) BFs[tid] = bf[tid];
    if (tid < 72) BLs[tid] = (tid < 65) ? bl[tid] : 0.f;
    __syncthreads();

    for (int i = tid; i < VOCAB * NE; i += 512) {
        int tok = i >> 5, n = i & 31;
        int h = n >> 3, d = n & 7;
        float a = 0.f;
        #pragma unroll
        for (int c = 0; c < NE; c++)
            a = fmaf(sTE[tok * NE + c], sWV[(h * NE + c) * 8 + d], a);
        sTV[i] = a;
    }
    if (tid < 256) {
        int s = tid >> 5, n = tid & 31;
        int h = n >> 3, d = n & 7;
        float a = 0.f;
        #pragma unroll
        for (int c = 0; c < NE; c++)
            a = fmaf(pos_emb[s * NE + c], sWV[(h * NE + c) * 8 + d], a);
        sPV[tid] = a;
    }
    __syncthreads();

    for (int i = tid; i < NROWTAB * NE; i += 512) {
        int r = i >> 5, n = i & 31;
        int s = r / VOCAB, tok = r - s * VOCAB;
        VT[r * VT_STRIDE + n] = sTV[tok * NE + n] + sPV[s * NE + n];
    }

    // B1P: fp16 B fragments of WfT, both k-blocks per entry.
    if (tid < 128) {
        int ent = tid;
        int lr = ent & 3, lq = (ent >> 2) & 7, nt = ent >> 5;
        int n  = nt * 8 + lq;
        int e0 = 2 * lr, e1 = 16 + 2 * lr;
        uint4 q;
        q.x = pkhf(Wf[e0 * NE + n],       Wf[(e0 + 1) * NE + n]);
        q.y = pkhf(Wf[(e0 + 8) * NE + n], Wf[(e0 + 9) * NE + n]);
        q.z = pkhf(Wf[e1 * NE + n],       Wf[(e1 + 1) * NE + n]);
        q.w = pkhf(Wf[(e1 + 8) * NE + n], Wf[(e1 + 9) * NE + n]);
        B1P[ent] = q;
    }
    // B2P: same for WlT (N padded to 72, cols >= 65 zero)
    if (tid < 288) {
        int ent = tid;
        int lr = ent & 3, lq = (ent >> 2) & 7, nt = ent >> 5;
        int n  = nt * 8 + lq;
        int e0 = 2 * lr, e1 = 16 + 2 * lr;
        uint4 q = make_uint4(0u, 0u, 0u, 0u);
        if (n < 65) {
            q.x = pkhf(Wl[e0 * VOCAB + n],       Wl[(e0 + 1) * VOCAB + n]);
            q.y = pkhf(Wl[(e0 + 8) * VOCAB + n], Wl[(e0 + 9) * VOCAB + n]);
            q.z = pkhf(Wl[e1 * VOCAB + n],       Wl[(e1 + 1) * VOCAB + n]);
            q.w = pkhf(Wl[(e1 + 8) * VOCAB + n], Wl[(e1 + 9) * VOCAB + n]);
        }
        B2P[ent] = q;
    }
    __syncthreads();

    const int wid = tid >> 5, l = tid & 31;
    const int lq = l >> 2, lr = l & 3;
    const int t = l & 7;
    char*     WR = sm + OFF_WARP + wid * WARP_BYTES;
    uint32_t* XW = (uint32_t*)WR;      // 32 rows * 20 words (A-frag staging)
    float*    ST = (float*)WR;         // 16 rows * 65 floats (stage, aliased)

    const int wstride = gridDim.x * NWARP;
    int wt = blockIdx.x * NWARP + wid;
    if (wt < n_wtiles) {
        // ---- peel: first tile's tokens + QK lookups ----
        int tk = idx[(size_t)wt * 32 + l];
        float4 w4[8];
        {
            int tks[8];
            #pragma unroll
            for (int s = 0; s < 8; s++) tks[s] = __shfl_sync(0xffffffffu, tk, (l & 24) | s);
            #pragma unroll
            for (int s = 0; s < 8; s++)
                if (s <= t)
                    w4[s] = g_qk[((t * VOCAB + tks[t]) * 8 + s) * VOCAB + tks[s]];
        }

        while (wt < n_wtiles) {
            const int wtn = wt + wstride;

            // ---- tokens (recomputed from tk; cheap shuffles) ----
            int toks[8];
            #pragma unroll
            for (int s = 0; s < 8; s++)
                toks[s] = __shfl_sync(0xffffffffu, tk, (l & 24) | s);

            // ---- prefetch next tile's idx ----
            int tk_next = 0;
            if (wtn < n_wtiles) tk_next = idx[(size_t)wtn * 32 + l];

            // ---- attention: softmax from prefetched w4 + smem V-sum ----
            float x2[32];
            #pragma unroll
            for (int h = 0; h < 4; h++) {
                float p[8], ssum = 0.f;
                #pragma unroll
                for (int s = 0; s < 8; s++) {
                    if (s <= t) {
                        p[s] = (h == 0) ? w4[s].x : (h == 1) ? w4[s].y
                             : (h == 2) ? w4[s].z : w4[s].w;
                        ssum += p[s];
                    }
                }
                float inv = __fdividef(1.f, ssum);
                float oh[8] = {0.f, 0.f, 0.f, 0.f, 0.f, 0.f, 0.f, 0.f};
                #pragma unroll
                for (int s = 0; s < 8; s++) {
                    if (s <= t) {
                        const float* vr = &VT[(s * VOCAB + toks[s]) * VT_STRIDE + h * 8];
                        float4 v0 = *reinterpret_cast<const float4*>(vr);
                        float4 v1 = *reinterpret_cast<const float4*>(vr + 4);
                        float ws = p[s];
                        oh[0] = fmaf(ws, v0.x, oh[0]); oh[1] = fmaf(ws, v0.y, oh[1]);
                        oh[2] = fmaf(ws, v0.z, oh[2]); oh[3] = fmaf(ws, v0.w, oh[3]);
                        oh[4] = fmaf(ws, v1.x, oh[4]); oh[5] = fmaf(ws, v1.y, oh[5]);
                        oh[6] = fmaf(ws, v1.z, oh[6]); oh[7] = fmaf(ws, v1.w, oh[7]);
                    }
                }
                #pragma unroll
                for (int d = 0; d < 8; d++) x2[h * 8 + d] = oh[d] * inv;
            }

            // ---- stage x2 as fp16x2: 4 STS.128 (rows 80B) ----
            {
                uint32_t xh[16];
                #pragma unroll
                for (int p = 0; p < 16; p++) xh[p] = pkhf(x2[2 * p], x2[2 * p + 1]);
                uint4* xr4 = (uint4*)(XW + l * 20);
                #pragma unroll
                for (int q = 0; q < 4; q++)
                    xr4[q] = make_uint4(xh[4 * q], xh[4 * q + 1], xh[4 * q + 2], xh[4 * q + 3]);
            }
            __syncwarp();

            // ---- A fragments for GEMM1 ----
            uint32_t ah[2][2][4];
            #pragma unroll
            for (int m = 0; m < 2; m++) {
                int r0 = (m * 16 + lq) * 20, r1 = r0 + 8 * 20;
                #pragma unroll
                for (int k = 0; k < 2; k++) {
                    int w0 = 8 * k + lr;
                    ah[m][k][0] = XW[r0 + w0];     ah[m][k][1] = XW[r1 + w0];
                    ah[m][k][2] = XW[r0 + w0 + 4]; ah[m][k][3] = XW[r1 + w0 + 4];
                }
            }
            __syncwarp();   // XW reads done; region reused as ST below

            // ---- issue next tile's QK lookups: drain behind the GEMM phase ----
            float4 w4n[8];
            if (wtn < n_wtiles) {
                int tksn[8];
                #pragma unroll
                for (int s = 0; s < 8; s++)
                    tksn[s] = __shfl_sync(0xffffffffu, tk_next, (l & 24) | s);
                #pragma unroll
                for (int s = 0; s < 8; s++)
                    if (s <= t)
                        w4n[s] = g_qk[((t * VOCAB + tksn[t]) * 8 + s) * VOCAB + tksn[s]];
            }

            // ---- GEMM1: D1 = X @ WfT (fp16, 16 MMA) ----
            float D1[2][4][4];
            #pragma unroll
            for (int m = 0; m < 2; m++)
                #pragma unroll
                for (int n = 0; n < 4; n++)
                    #pragma unroll
                    for (int q = 0; q < 4; q++) D1[m][n][q] = 0.f;

            #pragma unroll
            for (int nt = 0; nt < 4; nt++) {
                uint4 b = B1P[(nt * 8 + lq) * 4 + lr];
                #pragma unroll
                for (int m = 0; m < 2; m++) {
                    mma16816(D1[m][nt], ah[m][0], b.x, b.y);
                    mma16816(D1[m][nt], ah[m][1], b.z, b.w);
                }
            }

            // ---- relu(+bias) -> GEMM2 A fragments (registers only) ----
            uint32_t fh[2][2][4];
            #pragma unroll
            for (int m = 0; m < 2; m++) {
                #pragma unroll
                for (int nt = 0; nt < 4; nt++) {
                    int col = nt * 8 + lr * 2;
                    float c0 = fmaxf(D1[m][nt][0] + BFs[col],     0.f);
                    float c1 = fmaxf(D1[m][nt][1] + BFs[col + 1], 0.f);
                    float c2 = fmaxf(D1[m][nt][2] + BFs[col],     0.f);
                    float c3 = fmaxf(D1[m][nt][3] + BFs[col + 1], 0.f);
                    int K = nt >> 1, pc = nt & 1;
                    fh[m][K][2 * pc]     = pkhf(c0, c1);
                    fh[m][K][2 * pc + 1] = pkhf(c2, c3);
                }
            }

            // ---- GEMM2 per m-half: 36 MMA total -> stride-65 stage -> flush ----
            #pragma unroll
            for (int m = 0; m < 2; m++) {
                #pragma unroll
                for (int nt = 0; nt < 9; nt++) {
                    uint4 b = B2P[(nt * 8 + lq) * 4 + lr];
                    float D2[4] = {0.f, 0.f, 0.f, 0.f};
                    mma16816(D2, fh[m][0], b.x, b.y);
                    mma16816(D2, fh[m][1], b.z, b.w);
                    int col = nt * 8 + lr * 2;
                    int r0 = lq * 65, r1 = r0 + 8 * 65;
                    if (nt < 8) {
                        // scalar stores (odd-lq float2 would be misaligned)
                        ST[r0 + col]     = D2[0] + BLs[col];
                        ST[r0 + col + 1] = D2[1] + BLs[col + 1];
                        ST[r1 + col]     = D2[2] + BLs[col];
                        ST[r1 + col + 1] = D2[3] + BLs[col + 1];
                    } else if (lr == 0) {
                        ST[r0 + 64] = D2[0] + BLs[64];
                        ST[r1 + 64] = D2[2] + BLs[64];
                    }
                }
                __syncwarp();

                // contiguous flush: 16 rows * 65 f = 260 float4
                float4*       og = (float4*)(out + ((size_t)wt * 32 + m * 16) * 65);
                const float4* s4 = (const float4*)ST;
                #pragma unroll
                for (int i = 0; i < 8; i++) og[i * 32 + l] = s4[i * 32 + l];
                if (l < 4) og[256 + l] = s4[256 + l];
                __syncwarp();
            }

            // ---- rotate pipeline state ----
            wt = wtn;
            tk = tk_next;
            #pragma unroll
            for (int s = 0; s < 8; s++) w4[s] = w4n[s];
        }
    }
}

// ---------------- launch ----------------
extern "C" void kernel_launch(void* const* d_in, const int* in_sizes, int n_in,
                              void* d_out, int out_size) {
    const int*   idx     = (const int*)  d_in[0];
    const float* tok_emb = (const float*)d_in[1];
    const float* pos_emb = (const float*)d_in[2];
    const float* Wq      = (const float*)d_in[3];
    const float* Wk      = (const float*)d_in[4];
    const float* Wv      = (const float*)d_in[5];
    const float* Wf      = (const float*)d_in[6];
    const float* bf      = (const float*)d_in[7];
    const float* Wl      = (const float*)d_in[8];
    const float* bl      = (const float*)d_in[9];
    float* out = (float*)d_out;

    build_qk_fused<<<64, 256>>>(tok_emb, pos_emb, Wq, Wk);

    int dev = 0, smc = 148;
    cudaGetDevice(&dev);
    cudaDeviceGetAttribute(&smc, cudaDevAttrMultiProcessorCount, dev);

    cudaFuncSetAttribute(bigram_main,
                         cudaFuncAttributeMaxDynamicSharedMemorySize, SMEM_TOTAL);
    int n_wtiles = in_sizes[0] / 32;     // 1,048,576 / 32 = 32768
    bigram_main<<<smc, 512, SMEM_TOTAL>>>(idx, tok_emb, pos_emb, Wv,
                                          Wf, bf, Wl, bl, out, n_wtiles);
}